// round 15
// baseline (speedup 1.0000x reference)
#include <cuda_runtime.h>
#include <math.h>
#include <stdint.h>

#define BATCH       4096
#define INPUT_DIM   1568
#define HIDDEN      256
#define NUM_LATENTS 98
#define EMBED_DIM   16
#define LATDIM      (NUM_LATENTS * EMBED_DIM)   // 1568
#define NUM_EMB     512
#define NROWS       (BATCH * NUM_LATENTS)       // 401408
#define VQ_THREADS  256
#define VQ_BLOCKS   (NROWS / 4 / VQ_THREADS)    // 392

// ---------------- scratch (device globals; no allocation allowed) ----------
__device__ float g_h [BATCH * HIDDEN];
__device__ float g_ze[BATCH * LATDIM];
__device__ float g_q [BATCH * LATDIM];     // holds q_st (decoder input)
__device__ float g_h2[BATCH * HIDDEN];
__device__ float g_sqpart[VQ_BLOCKS];
__device__ int   g_maxidx[NUM_LATENTS];

// ---------------- init ------------------------------------------------------
__global__ void init_kernel() {
    int t = threadIdx.x;
    if (t < NUM_LATENTS) g_maxidx[t] = 0;
}

// Sequential ascending adds of rounded squares (R2 canonical form:
// square op materialized, then separate sequential reduce).
__device__ __forceinline__ float seq_rowsum16_sq(const float* e) {
    float acc = 0.f;
    #pragma unroll
    for (int d = 0; d < 16; d++)
        acc = __fadd_rn(acc, __fmul_rn(e[d], e[d]));
    return acc;
}

// ---------------- SGEMM (NT): C[M,N] = A[M,K] * B[N,K]^T + bias, opt. ReLU ---
// KC = 0 : single ascending-k FMA chain per element.
// KC > 0 : Eigen TensorContraction kc-blocking — gebp panel of length KC is
//          an ascending FMA chain; panels folded into the C value in order:
//          C = fl(fl(p0+p1)+p2)...  (fp32 C-buffer read-modify-write)
template<int RELU, int KC>
__global__ __launch_bounds__(256)
void sgemm_nt(const float* __restrict__ A, const float* __restrict__ B,
              const float* __restrict__ bias, float* __restrict__ C,
              int M, int N, int K)
{
    __shared__ float As[8][128];
    __shared__ float Bs[8][128];

    const int tid = threadIdx.x;
    const int bm  = blockIdx.y * 128;
    const int bn  = blockIdx.x * 128;
    const int tr  = (tid >> 4) * 8;
    const int tc  = (tid & 15) * 8;
    const int lr  = tid >> 1;
    const int lc  = (tid & 1) * 4;

    const float* Ap = A + (size_t)(bm + lr) * K + lc;
    const bool   bval = (bn + lr) < N;
    const float* Bp = B + (size_t)(bn + lr) * K + lc;

    float acc[8][8];
    float tot[KC ? 8 : 1][KC ? 8 : 1];
    #pragma unroll
    for (int i = 0; i < 8; i++)
        #pragma unroll
        for (int j = 0; j < 8; j++) acc[i][j] = 0.f;
    if (KC) {
        #pragma unroll
        for (int i = 0; i < (KC ? 8 : 1); i++)
            #pragma unroll
            for (int j = 0; j < (KC ? 8 : 1); j++) tot[i][j] = 0.f;
    }

    for (int k0 = 0; k0 < K; k0 += 8) {
        float4 av = *(const float4*)(Ap + k0);
        float4 bv = bval ? *(const float4*)(Bp + k0) : make_float4(0.f, 0.f, 0.f, 0.f);
        As[lc + 0][lr] = av.x; As[lc + 1][lr] = av.y;
        As[lc + 2][lr] = av.z; As[lc + 3][lr] = av.w;
        Bs[lc + 0][lr] = bv.x; Bs[lc + 1][lr] = bv.y;
        Bs[lc + 2][lr] = bv.z; Bs[lc + 3][lr] = bv.w;
        __syncthreads();
        #pragma unroll
        for (int kk = 0; kk < 8; kk++) {
            float ar[8], br[8];
            #pragma unroll
            for (int i = 0; i < 8; i++) ar[i] = As[kk][tr + i];
            #pragma unroll
            for (int j = 0; j < 8; j++) br[j] = Bs[kk][tc + j];
            #pragma unroll
            for (int i = 0; i < 8; i++)
                #pragma unroll
                for (int j = 0; j < 8; j++)
                    acc[i][j] = __fmaf_rn(ar[i], br[j], acc[i][j]);
        }
        __syncthreads();
        if (KC && (((k0 + 8) % (KC ? KC : 1)) == 0)) {   // gebp panel boundary
            #pragma unroll
            for (int i = 0; i < (KC ? 8 : 1); i++)
                #pragma unroll
                for (int j = 0; j < (KC ? 8 : 1); j++) {
                    tot[i][j] = __fadd_rn(tot[i][j], acc[i][j]);  // first: fl(0+p0)=p0
                    acc[i][j] = 0.f;
                }
        }
    }
    if (KC && (K % (KC ? KC : 1)) != 0) {   // tail panel fold (1568%512=544 tail)
        #pragma unroll
        for (int i = 0; i < (KC ? 8 : 1); i++)
            #pragma unroll
            for (int j = 0; j < (KC ? 8 : 1); j++)
                tot[i][j] = __fadd_rn(tot[i][j], acc[i][j]);
    }

    #pragma unroll
    for (int j = 0; j < 8; j++) {
        int n = bn + tc + j;
        if (n >= N) continue;
        float bsv = bias[n];
        #pragma unroll
        for (int i = 0; i < 8; i++) {
            float r = KC ? tot[KC ? i : 0][KC ? j : 0] : acc[i][j];
            float v = __fadd_rn(r, bsv);
            if (RELU) v = fmaxf(v, 0.f);
            C[(size_t)(bm + tr + i) * N + n] = v;
        }
    }
}

// ---------------- VQ: R2 canonical reference-form distance -------------------
// dist = fl( fl(s1 + s2) - 2*g )   (2*g exact)
//   s1, s2: sequential ascending adds of rounded squares
//   g : ascending fp32 FMA chain (Eigen gebp K=16 accumulation)
// argmin strict < scanning c ascending (first-index tie-break).
__global__ __launch_bounds__(VQ_THREADS)
void vq_kernel(const float* __restrict__ ze, const float* __restrict__ codebook,
               float* __restrict__ qst, float* __restrict__ out_idx)
{
    __shared__ __align__(16) float sc[NUM_EMB * 16];
    __shared__ float s2s[NUM_EMB];
    __shared__ float ssq[VQ_THREADS / 32];

    const int tid = threadIdx.x;

    for (int i = tid; i < NUM_EMB * 4; i += VQ_THREADS)
        ((float4*)sc)[i] = ((const float4*)codebook)[i];
    __syncthreads();
    for (int c = tid; c < NUM_EMB; c += VQ_THREADS)
        s2s[c] = seq_rowsum16_sq(sc + c * 16);
    __syncthreads();

    const int gthread = blockIdx.x * VQ_THREADS + tid;
    const int r0 = gthread * 4;

    float z[4][16];
    #pragma unroll
    for (int r = 0; r < 4; r++) {
        const float4* zp = (const float4*)(ze + (size_t)(r0 + r) * 16);
        #pragma unroll
        for (int v = 0; v < 4; v++) {
            float4 t = zp[v];
            z[r][v * 4 + 0] = t.x; z[r][v * 4 + 1] = t.y;
            z[r][v * 4 + 2] = t.z; z[r][v * 4 + 3] = t.w;
        }
    }

    float s1[4];
    #pragma unroll
    for (int r = 0; r < 4; r++)
        s1[r] = seq_rowsum16_sq(z[r]);

    float best[4] = { __int_as_float(0x7f800000), __int_as_float(0x7f800000),
                      __int_as_float(0x7f800000), __int_as_float(0x7f800000) };
    int bidx[4] = {0, 0, 0, 0};

    #pragma unroll 2
    for (int c = 0; c < NUM_EMB; c++) {
        const float4* cp = (const float4*)(sc + c * 16);
        float4 c0 = cp[0], c1 = cp[1], c2 = cp[2], c3 = cp[3];
        float cd[16] = { c0.x, c0.y, c0.z, c0.w, c1.x, c1.y, c1.z, c1.w,
                         c2.x, c2.y, c2.z, c2.w, c3.x, c3.y, c3.z, c3.w };
        const float s2c = s2s[c];
        #pragma unroll
        for (int r = 0; r < 4; r++) {
            float g = 0.f;
            #pragma unroll
            for (int d = 0; d < 16; d++)
                g = __fmaf_rn(z[r][d], cd[d], g);
            float t    = __fadd_rn(s1[r], s2c);
            float dist = __fsub_rn(t, __fmul_rn(2.0f, g));
            if (dist < best[r]) { best[r] = dist; bidx[r] = c; }
        }
    }

    float sqacc = 0.f;
    #pragma unroll
    for (int r = 0; r < 4; r++) {
        const int row = r0 + r;
        const int bi  = bidx[r];
        float* qp = qst + (size_t)row * 16;
        float acc = 0.f;
        #pragma unroll
        for (int d = 0; d < 16; d++) {
            float qv = sc[bi * 16 + d];
            float dd = __fsub_rn(qv, z[r][d]);          // fl(q - z)
            qp[d] = __fadd_rn(z[r][d], dd);             // q_st = fl(z + fl(q-z))
            acc = __fadd_rn(acc, __fmul_rn(dd, dd));
        }
        out_idx[row] = (float)bidx[r];
        atomicMax(&g_maxidx[row % NUM_LATENTS], bi);
        sqacc += acc;
    }

    #pragma unroll
    for (int off = 16; off > 0; off >>= 1)
        sqacc += __shfl_xor_sync(0xffffffffu, sqacc, off);
    if ((tid & 31) == 0) ssq[tid >> 5] = sqacc;
    __syncthreads();
    if (tid == 0) {
        float s = 0.f;
        for (int w = 0; w < VQ_THREADS / 32; w++) s += ssq[w];
        g_sqpart[blockIdx.x] = s;
    }
}

// ---------------- finalize: vq_loss + perplexity ----------------------------
__global__ void finalize_kernel(float* __restrict__ out_loss,
                                float* __restrict__ out_perp)
{
    int tid = threadIdx.x;
    if (tid == 0) {
        double s = 0.0;
        for (int i = 0; i < VQ_BLOCKS; i++) s += (double)g_sqpart[i];
        double mse = s / (double)((size_t)BATCH * NUM_LATENTS * EMBED_DIM);
        *out_loss = (float)(1.25 * mse);   // q_latent + COMMIT*e_latent (identical terms)
    }
    if (tid == 1) {
        double p = 0.0;
        for (int l = 0; l < NUM_LATENTS; l++) {
            float a = 1.0f / ((float)g_maxidx[l] + 1.0f);
            p += (double)expf(-a * logf(a + 1e-10f));
        }
        *out_perp = (float)(p / (double)NUM_LATENTS);
    }
}

// ---------------- launch -----------------------------------------------------
extern "C" void kernel_launch(void* const* d_in, const int* in_sizes, int n_in,
                              void* d_out, int out_size)
{
    const float* x   = (const float*)d_in[0];
    const float* We1 = (const float*)d_in[1];
    const float* be1 = (const float*)d_in[2];
    const float* We2 = (const float*)d_in[3];
    const float* be2 = (const float*)d_in[4];
    const float* cb  = (const float*)d_in[5];
    const float* Wd1 = (const float*)d_in[6];
    const float* bd1 = (const float*)d_in[7];
    const float* Wd2 = (const float*)d_in[8];
    const float* bd2 = (const float*)d_in[9];

    float* out     = (float*)d_out;
    float* x_recon = out;                                   // [4096*1568]
    float* loss    = out + (size_t)BATCH * INPUT_DIM;       // [1]
    float* perp    = loss + 1;                              // [1]
    float* idxo    = perp + 1;                              // [4096*98]

    float *ph, *pze, *pq, *ph2;
    cudaGetSymbolAddress((void**)&ph,  g_h);
    cudaGetSymbolAddress((void**)&pze, g_ze);
    cudaGetSymbolAddress((void**)&pq,  g_q);
    cudaGetSymbolAddress((void**)&ph2, g_h2);

    init_kernel<<<1, 128>>>();

    // encoder L1 (K=1568): Eigen TensorContraction kc=512 blocking —
    // panels [0,512),[512,1024),[1024,1568), running fold into C
    sgemm_nt<1, 512><<<dim3(2, 32), 256>>>(x, We1, be1, ph, BATCH, HIDDEN, INPUT_DIM);
    // z_e (K=256 <= kc): single ascending chain
    sgemm_nt<0, 0><<<dim3(13, 32), 256>>>(ph, We2, be2, pze, BATCH, LATDIM, HIDDEN);

    // VQ (R2 canonical forms); writes q_st
    vq_kernel<<<VQ_BLOCKS, VQ_THREADS>>>(pze, cb, pq, idxo);

    // scalars
    finalize_kernel<<<1, 32>>>(loss, perp);

    // decoder (continuous path; accumulation micro-structure immaterial)
    sgemm_nt<1, 0><<<dim3(2, 32), 256>>>(pq, Wd1, bd1, ph2, BATCH, HIDDEN, LATDIM);
    sgemm_nt<0, 0><<<dim3(13, 32), 256>>>(ph2, Wd2, bd2, x_recon, BATCH, INPUT_DIM, HIDDEN);
}

// round 16
// speedup vs baseline: 1.2733x; 1.2733x over previous
#include <cuda_runtime.h>
#include <math.h>
#include <stdint.h>

#define BATCH       4096
#define INPUT_DIM   1568
#define HIDDEN      256
#define NUM_LATENTS 98
#define EMBED_DIM   16
#define LATDIM      (NUM_LATENTS * EMBED_DIM)   // 1568
#define NUM_EMB     512
#define NROWS       (BATCH * NUM_LATENTS)       // 401408
#define VQ_THREADS  256
#define VQ_RPT      2                            // rows per thread
#define VQ_BLOCKS   (NROWS / VQ_RPT / VQ_THREADS)  // 784

// ---------------- scratch (device globals; no allocation allowed) ----------
__device__ float g_h [BATCH * HIDDEN];
__device__ float g_ze[BATCH * LATDIM];
__device__ float g_q [BATCH * LATDIM];     // holds q_st (decoder input)
__device__ float g_h2[BATCH * HIDDEN];
__device__ float g_sqpart[VQ_BLOCKS];
__device__ int   g_maxidx[NUM_LATENTS];

// ---------------- init ------------------------------------------------------
__global__ void init_kernel() {
    int t = threadIdx.x;
    if (t < NUM_LATENTS) g_maxidx[t] = 0;
}

// Sequential ascending adds of rounded squares (reference form).
__device__ __forceinline__ float seq_rowsum16_sq(const float* e) {
    float acc = 0.f;
    #pragma unroll
    for (int d = 0; d < 16; d++)
        acc = __fadd_rn(acc, __fmul_rn(e[d], e[d]));
    return acc;
}

// ---------------- SGEMM (NT) 128x128 tile: C = A*B^T + bias ------------------
// KC = 0: single ascending-k FMA chain. KC > 0: Eigen kc panel folds.
template<int RELU, int KC>
__global__ __launch_bounds__(256)
void sgemm_nt(const float* __restrict__ A, const float* __restrict__ B,
              const float* __restrict__ bias, float* __restrict__ C,
              int M, int N, int K)
{
    __shared__ float As[8][128];
    __shared__ float Bs[8][128];

    const int tid = threadIdx.x;
    const int bm  = blockIdx.y * 128;
    const int bn  = blockIdx.x * 128;
    const int tr  = (tid >> 4) * 8;
    const int tc  = (tid & 15) * 8;
    const int lr  = tid >> 1;
    const int lc  = (tid & 1) * 4;

    const float* Ap = A + (size_t)(bm + lr) * K + lc;
    const bool   bval = (bn + lr) < N;
    const float* Bp = B + (size_t)(bn + lr) * K + lc;

    float acc[8][8];
    float tot[KC ? 8 : 1][KC ? 8 : 1];
    #pragma unroll
    for (int i = 0; i < 8; i++)
        #pragma unroll
        for (int j = 0; j < 8; j++) acc[i][j] = 0.f;
    if (KC) {
        #pragma unroll
        for (int i = 0; i < (KC ? 8 : 1); i++)
            #pragma unroll
            for (int j = 0; j < (KC ? 8 : 1); j++) tot[i][j] = 0.f;
    }

    for (int k0 = 0; k0 < K; k0 += 8) {
        float4 av = *(const float4*)(Ap + k0);
        float4 bv = bval ? *(const float4*)(Bp + k0) : make_float4(0.f, 0.f, 0.f, 0.f);
        As[lc + 0][lr] = av.x; As[lc + 1][lr] = av.y;
        As[lc + 2][lr] = av.z; As[lc + 3][lr] = av.w;
        Bs[lc + 0][lr] = bv.x; Bs[lc + 1][lr] = bv.y;
        Bs[lc + 2][lr] = bv.z; Bs[lc + 3][lr] = bv.w;
        __syncthreads();
        #pragma unroll
        for (int kk = 0; kk < 8; kk++) {
            float ar[8], br[8];
            #pragma unroll
            for (int i = 0; i < 8; i++) ar[i] = As[kk][tr + i];
            #pragma unroll
            for (int j = 0; j < 8; j++) br[j] = Bs[kk][tc + j];
            #pragma unroll
            for (int i = 0; i < 8; i++)
                #pragma unroll
                for (int j = 0; j < 8; j++)
                    acc[i][j] = __fmaf_rn(ar[i], br[j], acc[i][j]);
        }
        __syncthreads();
        if (KC && (((k0 + 8) % (KC ? KC : 1)) == 0)) {
            #pragma unroll
            for (int i = 0; i < (KC ? 8 : 1); i++)
                #pragma unroll
                for (int j = 0; j < (KC ? 8 : 1); j++) {
                    tot[i][j] = __fadd_rn(tot[i][j], acc[i][j]);
                    acc[i][j] = 0.f;
                }
        }
    }
    if (KC && (K % (KC ? KC : 1)) != 0) {
        #pragma unroll
        for (int i = 0; i < (KC ? 8 : 1); i++)
            #pragma unroll
            for (int j = 0; j < (KC ? 8 : 1); j++)
                tot[i][j] = __fadd_rn(tot[i][j], acc[i][j]);
    }

    #pragma unroll
    for (int j = 0; j < 8; j++) {
        int n = bn + tc + j;
        if (n >= N) continue;
        float bsv = bias[n];
        #pragma unroll
        for (int i = 0; i < 8; i++) {
            float r = KC ? tot[KC ? i : 0][KC ? j : 0] : acc[i][j];
            float v = __fadd_rn(r, bsv);
            if (RELU) v = fmaxf(v, 0.f);
            C[(size_t)(bm + tr + i) * N + n] = v;
        }
    }
}

// ---------------- SGEMM (NT) 128x64 tile — for N=256 GEMMs (2x the CTAs) ----
// Identical per-element k-chain arithmetic (ascending FMA + optional kc folds).
template<int RELU, int KC>
__global__ __launch_bounds__(256)
void sgemm_nt_n64(const float* __restrict__ A, const float* __restrict__ B,
                  const float* __restrict__ bias, float* __restrict__ C,
                  int M, int N, int K)
{
    __shared__ float As[8][128];
    __shared__ float Bs[8][64];

    const int tid = threadIdx.x;
    const int bm  = blockIdx.y * 128;
    const int bn  = blockIdx.x * 64;
    const int tr  = (tid >> 4) * 8;        // 16 row groups of 8
    const int tc  = (tid & 15) * 4;        // 16 col groups of 4
    const int lrA = tid >> 1;              // 0..127
    const int lcA = (tid & 1) * 4;
    const int lrB = tid >> 2;              // 0..63
    const int lcB = (tid & 3) * 2;

    const float* Ap = A + (size_t)(bm + lrA) * K + lcA;
    const float* Bp = B + (size_t)(bn + lrB) * K + lcB;

    float acc[8][4];
    float tot[KC ? 8 : 1][KC ? 4 : 1];
    #pragma unroll
    for (int i = 0; i < 8; i++)
        #pragma unroll
        for (int j = 0; j < 4; j++) acc[i][j] = 0.f;
    if (KC) {
        #pragma unroll
        for (int i = 0; i < (KC ? 8 : 1); i++)
            #pragma unroll
            for (int j = 0; j < (KC ? 4 : 1); j++) tot[i][j] = 0.f;
    }

    for (int k0 = 0; k0 < K; k0 += 8) {
        float4 av = *(const float4*)(Ap + k0);
        float2 bv = *(const float2*)(Bp + k0);
        As[lcA + 0][lrA] = av.x; As[lcA + 1][lrA] = av.y;
        As[lcA + 2][lrA] = av.z; As[lcA + 3][lrA] = av.w;
        Bs[lcB + 0][lrB] = bv.x; Bs[lcB + 1][lrB] = bv.y;
        __syncthreads();
        #pragma unroll
        for (int kk = 0; kk < 8; kk++) {
            float ar[8], br[4];
            #pragma unroll
            for (int i = 0; i < 8; i++) ar[i] = As[kk][tr + i];
            #pragma unroll
            for (int j = 0; j < 4; j++) br[j] = Bs[kk][tc + j];
            #pragma unroll
            for (int i = 0; i < 8; i++)
                #pragma unroll
                for (int j = 0; j < 4; j++)
                    acc[i][j] = __fmaf_rn(ar[i], br[j], acc[i][j]);
        }
        __syncthreads();
        if (KC && (((k0 + 8) % (KC ? KC : 1)) == 0)) {
            #pragma unroll
            for (int i = 0; i < (KC ? 8 : 1); i++)
                #pragma unroll
                for (int j = 0; j < (KC ? 4 : 1); j++) {
                    tot[i][j] = __fadd_rn(tot[i][j], acc[i][j]);
                    acc[i][j] = 0.f;
                }
        }
    }
    if (KC && (K % (KC ? KC : 1)) != 0) {
        #pragma unroll
        for (int i = 0; i < (KC ? 8 : 1); i++)
            #pragma unroll
            for (int j = 0; j < (KC ? 4 : 1); j++)
                tot[i][j] = __fadd_rn(tot[i][j], acc[i][j]);
    }

    #pragma unroll
    for (int j = 0; j < 4; j++) {
        int n = bn + tc + j;
        float bsv = bias[n];
        #pragma unroll
        for (int i = 0; i < 8; i++) {
            float r = KC ? tot[KC ? i : 0][KC ? j : 0] : acc[i][j];
            float v = __fadd_rn(r, bsv);
            if (RELU) v = fmaxf(v, 0.f);
            C[(size_t)(bm + tr + i) * N + n] = v;
        }
    }
}

// ---------------- VQ: reference-form distance, 2 rows/thread -----------------
// dist = fl( fl(s1 + s2) - 2*g ), s1/s2 sequential rounded squares,
// g ascending FMA chain; argmin strict < ascending c.
__global__ __launch_bounds__(VQ_THREADS)
void vq_kernel(const float* __restrict__ ze, const float* __restrict__ codebook,
               float* __restrict__ qst, float* __restrict__ out_idx)
{
    __shared__ __align__(16) float sc[NUM_EMB * 16];
    __shared__ float s2s[NUM_EMB];
    __shared__ float ssq[VQ_THREADS / 32];

    const int tid = threadIdx.x;

    for (int i = tid; i < NUM_EMB * 4; i += VQ_THREADS)
        ((float4*)sc)[i] = ((const float4*)codebook)[i];
    __syncthreads();
    for (int c = tid; c < NUM_EMB; c += VQ_THREADS)
        s2s[c] = seq_rowsum16_sq(sc + c * 16);
    __syncthreads();

    const int gthread = blockIdx.x * VQ_THREADS + tid;
    const int r0 = gthread * VQ_RPT;

    float z[VQ_RPT][16];
    #pragma unroll
    for (int r = 0; r < VQ_RPT; r++) {
        const float4* zp = (const float4*)(ze + (size_t)(r0 + r) * 16);
        #pragma unroll
        for (int v = 0; v < 4; v++) {
            float4 t = zp[v];
            z[r][v * 4 + 0] = t.x; z[r][v * 4 + 1] = t.y;
            z[r][v * 4 + 2] = t.z; z[r][v * 4 + 3] = t.w;
        }
    }

    float s1[VQ_RPT];
    #pragma unroll
    for (int r = 0; r < VQ_RPT; r++)
        s1[r] = seq_rowsum16_sq(z[r]);

    float best[VQ_RPT];
    int   bidx[VQ_RPT];
    #pragma unroll
    for (int r = 0; r < VQ_RPT; r++) { best[r] = __int_as_float(0x7f800000); bidx[r] = 0; }

    #pragma unroll 2
    for (int c = 0; c < NUM_EMB; c++) {
        const float4* cp = (const float4*)(sc + c * 16);
        float4 c0 = cp[0], c1 = cp[1], c2 = cp[2], c3 = cp[3];
        float cd[16] = { c0.x, c0.y, c0.z, c0.w, c1.x, c1.y, c1.z, c1.w,
                         c2.x, c2.y, c2.z, c2.w, c3.x, c3.y, c3.z, c3.w };
        const float s2c = s2s[c];
        #pragma unroll
        for (int r = 0; r < VQ_RPT; r++) {
            float g = 0.f;
            #pragma unroll
            for (int d = 0; d < 16; d++)
                g = __fmaf_rn(z[r][d], cd[d], g);
            float t    = __fadd_rn(s1[r], s2c);
            float dist = __fsub_rn(t, __fmul_rn(2.0f, g));
            if (dist < best[r]) { best[r] = dist; bidx[r] = c; }
        }
    }

    float sqacc = 0.f;
    #pragma unroll
    for (int r = 0; r < VQ_RPT; r++) {
        const int row = r0 + r;
        const int bi  = bidx[r];
        float* qp = qst + (size_t)row * 16;
        float acc = 0.f;
        #pragma unroll
        for (int d = 0; d < 16; d++) {
            float qv = sc[bi * 16 + d];
            float dd = __fsub_rn(qv, z[r][d]);          // fl(q - z)
            qp[d] = __fadd_rn(z[r][d], dd);             // q_st = fl(z + fl(q-z))
            acc = __fadd_rn(acc, __fmul_rn(dd, dd));
        }
        out_idx[row] = (float)bidx[r];
        atomicMax(&g_maxidx[row % NUM_LATENTS], bi);
        sqacc += acc;
    }

    #pragma unroll
    for (int off = 16; off > 0; off >>= 1)
        sqacc += __shfl_xor_sync(0xffffffffu, sqacc, off);
    if ((tid & 31) == 0) ssq[tid >> 5] = sqacc;
    __syncthreads();
    if (tid == 0) {
        float s = 0.f;
        for (int w = 0; w < VQ_THREADS / 32; w++) s += ssq[w];
        g_sqpart[blockIdx.x] = s;
    }
}

// ---------------- finalize: vq_loss + perplexity ----------------------------
__global__ void finalize_kernel(float* __restrict__ out_loss,
                                float* __restrict__ out_perp)
{
    int tid = threadIdx.x;
    if (tid == 0) {
        double s = 0.0;
        for (int i = 0; i < VQ_BLOCKS; i++) s += (double)g_sqpart[i];
        double mse = s / (double)((size_t)BATCH * NUM_LATENTS * EMBED_DIM);
        *out_loss = (float)(1.25 * mse);   // q_latent + COMMIT*e_latent (identical terms)
    }
    if (tid == 1) {
        double p = 0.0;
        for (int l = 0; l < NUM_LATENTS; l++) {
            float a = 1.0f / ((float)g_maxidx[l] + 1.0f);
            p += (double)expf(-a * logf(a + 1e-10f));
        }
        *out_perp = (float)(p / (double)NUM_LATENTS);
    }
}

// ---------------- launch -----------------------------------------------------
extern "C" void kernel_launch(void* const* d_in, const int* in_sizes, int n_in,
                              void* d_out, int out_size)
{
    const float* x   = (const float*)d_in[0];
    const float* We1 = (const float*)d_in[1];
    const float* be1 = (const float*)d_in[2];
    const float* We2 = (const float*)d_in[3];
    const float* be2 = (const float*)d_in[4];
    const float* cb  = (const float*)d_in[5];
    const float* Wd1 = (const float*)d_in[6];
    const float* bd1 = (const float*)d_in[7];
    const float* Wd2 = (const float*)d_in[8];
    const float* bd2 = (const float*)d_in[9];

    float* out     = (float*)d_out;
    float* x_recon = out;                                   // [4096*1568]
    float* loss    = out + (size_t)BATCH * INPUT_DIM;       // [1]
    float* perp    = loss + 1;                              // [1]
    float* idxo    = perp + 1;                              // [4096*98]

    float *ph, *pze, *pq, *ph2;
    cudaGetSymbolAddress((void**)&ph,  g_h);
    cudaGetSymbolAddress((void**)&pze, g_ze);
    cudaGetSymbolAddress((void**)&pq,  g_q);
    cudaGetSymbolAddress((void**)&ph2, g_h2);

    init_kernel<<<1, 128>>>();

    // encoder L1 (K=1568): Eigen kc=512 panel folds — bit-critical path.
    // 128x64 tiles -> 128 CTAs (was 64): same per-element k-chain, 2x SMs.
    sgemm_nt_n64<1, 512><<<dim3(4, 32), 256>>>(x, We1, be1, ph, BATCH, HIDDEN, INPUT_DIM);
    // z_e (K=256 <= kc): single ascending chain — bit-critical, unchanged.
    sgemm_nt<0, 0><<<dim3(13, 32), 256>>>(ph, We2, be2, pze, BATCH, LATDIM, HIDDEN);

    // VQ (reference forms, 2 rows/thread for occupancy); writes q_st
    vq_kernel<<<VQ_BLOCKS, VQ_THREADS>>>(pze, cb, pq, idxo);

    // scalars
    finalize_kernel<<<1, 32>>>(loss, perp);

    // decoder (continuous path): 128x64 tiles for the N=256 GEMM
    sgemm_nt_n64<1, 0><<<dim3(4, 32), 256>>>(pq, Wd1, bd1, ph2, BATCH, HIDDEN, LATDIM);
    sgemm_nt<0, 0><<<dim3(13, 32), 256>>>(ph2, Wd2, bd2, x_recon, BATCH, INPUT_DIM, HIDDEN);
}